// round 1
// baseline (speedup 1.0000x reference)
#include <cuda_runtime.h>

#define BB      64     // batch
#define TT      32     // frames per clip
#define NMAXX   64     // max boxes per batch element
#define HH      256    // hidden_dim (output)
#define HID     128    // MLP mid dim
#define RT      32     // rows (boxes) per group
#define NTHREADS 512
#define HTSTRIDE 36    // padded row stride for hidden^T in smem

// packed box index -> output row base (local*B*T + b*T); +t added at use site
__device__ int g_orow[BB * NMAXX];

__global__ void setup_kernel(const int* __restrict__ npf) {
    __shared__ int sn[BB];
    int tid = threadIdx.x;
    if (tid < BB) sn[tid] = npf[tid];
    __syncthreads();
    if (tid < BB) {
        int start = 0;
        for (int i = 0; i < tid; ++i) start += sn[i];
        int nb = sn[tid];
        int base = tid * TT;
        for (int i = 0; i < nb; ++i)
            g_orow[start + i] = i * (BB * TT) + base;
    }
}

// zero only the invalid padded region: (b, slot >= n[b]) -> T*H contiguous floats
__global__ void zerofill_kernel(const int* __restrict__ npf, float* __restrict__ out) {
    int b    = blockIdx.x >> 6;
    int slot = blockIdx.x & 63;
    if (slot < npf[b]) return;
    float4* dst = reinterpret_cast<float4*>(
        out + ((size_t)slot * (BB * TT) + (size_t)b * TT) * HH);
    float4 z = make_float4(0.f, 0.f, 0.f, 0.f);
    const int n4 = TT * HH / 4;
    for (int i = threadIdx.x; i < n4; i += blockDim.x) dst[i] = z;
}

__global__ __launch_bounds__(NTHREADS, 1)
void mlp_scatter_kernel(const float* __restrict__ bbox,
                        const float* __restrict__ W1,
                        const float* __restrict__ b1,
                        const float* __restrict__ W2,
                        const float* __restrict__ b2,
                        float* __restrict__ out,
                        int N, int ngroups) {
    extern __shared__ float sm[];
    float* W2s = sm;                        // [128][256] = 32768 floats (128 KB)
    float* hT  = W2s + HID * HH;            // [128][36]  = 4608 floats
    float* xbs = hT  + HID * HTSTRIDE;      // [32][4]    = 128 floats
    float* W1s = xbs + RT * 4;              // [4][128]   = 512 floats
    float* b1s = W1s + 4 * HID;             // 128
    float* b2s = b1s + HID;                 // 256
    int*   orow = reinterpret_cast<int*>(b2s + HH); // 32 ints

    const int tid = threadIdx.x;

    // stage persistent weights into smem
    for (int i = tid; i < HID * HH / 4; i += NTHREADS)
        reinterpret_cast<float4*>(W2s)[i] = reinterpret_cast<const float4*>(W2)[i];
    for (int i = tid; i < 4 * HID; i += NTHREADS) W1s[i] = W1[i];
    if (tid < HID) b1s[tid] = b1[tid];
    if (tid < HH)  b2s[tid] = b2[tid];

    // thread tile: 4 rows x 4 cols; 8 row-groups x 64 col-groups = 512 threads
    const int cg = tid & 63;
    const int rg = tid >> 6;
    const int h0 = cg << 2;
    const int r0 = rg << 2;

    for (int g = blockIdx.x; g < ngroups; g += gridDim.x) {
        const int tile = g / TT;
        const int t    = g - tile * TT;
        const int n0   = tile * RT;

        __syncthreads();  // also covers persistent-weight visibility on first iter

        if (tid < RT * 4) {
            int r = tid >> 2, k = tid & 3;
            int n = n0 + r;
            xbs[tid] = (n < N) ? bbox[((size_t)n * TT + t) * 4 + k] : 0.f;
        } else if (tid < RT * 4 + RT) {
            int r = tid - RT * 4;
            int n = n0 + r;
            orow[r] = (n < N) ? (g_orow[n] + t) : -1;
        }
        __syncthreads();

        // hidden: hT[j][r] = relu(b1[j] + sum_k x[r][k] * W1[k][j])
        {
            int j   = tid & (HID - 1);
            int rg2 = tid >> 7;  // 0..3 -> 8 rows each
            float w0 = W1s[j], w1 = W1s[HID + j], w2 = W1s[2 * HID + j], w3 = W1s[3 * HID + j];
            float bb = b1s[j];
            #pragma unroll
            for (int i = 0; i < 8; ++i) {
                int r = (rg2 << 3) + i;
                float4 xv = *reinterpret_cast<float4*>(&xbs[r << 2]);
                float v = fmaf(xv.x, w0, fmaf(xv.y, w1, fmaf(xv.z, w2, fmaf(xv.w, w3, bb))));
                hT[j * HTSTRIDE + r] = fmaxf(v, 0.f);
            }
        }
        __syncthreads();

        // GEMM: acc[4][4] over j = 0..127
        float acc[4][4];
        #pragma unroll
        for (int a = 0; a < 4; ++a)
            #pragma unroll
            for (int c = 0; c < 4; ++c) acc[a][c] = 0.f;

        const float* hp = hT  + r0;
        const float* wp = W2s + h0;
        #pragma unroll 4
        for (int j = 0; j < HID; ++j) {
            float4 hv = *reinterpret_cast<const float4*>(hp + j * HTSTRIDE);  // broadcast
            float4 wv = *reinterpret_cast<const float4*>(wp + j * HH);        // conflict-free
            float hvv[4] = {hv.x, hv.y, hv.z, hv.w};
            float wvv[4] = {wv.x, wv.y, wv.z, wv.w};
            #pragma unroll
            for (int a = 0; a < 4; ++a)
                #pragma unroll
                for (int c = 0; c < 4; ++c)
                    acc[a][c] = fmaf(hvv[a], wvv[c], acc[a][c]);
        }

        // epilogue: + b2, scatter to out[(orow + t)*H + h]
        float4 bv = *reinterpret_cast<float4*>(&b2s[h0]);
        float bvv[4] = {bv.x, bv.y, bv.z, bv.w};
        #pragma unroll
        for (int a = 0; a < 4; ++a) {
            int row = orow[r0 + a];
            if (row >= 0) {
                float4 v;
                v.x = acc[a][0] + bvv[0];
                v.y = acc[a][1] + bvv[1];
                v.z = acc[a][2] + bvv[2];
                v.w = acc[a][3] + bvv[3];
                *reinterpret_cast<float4*>(&out[(size_t)row * HH + h0]) = v;
            }
        }
    }
}

extern "C" void kernel_launch(void* const* d_in, const int* in_sizes, int n_in,
                              void* d_out, int out_size) {
    const float* bbox = (const float*)d_in[0];
    const float* W1   = (const float*)d_in[1];
    const float* b1   = (const float*)d_in[2];
    const float* W2   = (const float*)d_in[3];
    const float* b2   = (const float*)d_in[4];
    const int*   npf  = (const int*)d_in[5];
    float* out = (float*)d_out;

    const int N = in_sizes[0] / (TT * 4);          // total boxes across batch
    const int ntiles  = (N + RT - 1) / RT;
    const int ngroups = ntiles * TT;

    const size_t smem_bytes =
        (size_t)(HID * HH + HID * HTSTRIDE + RT * 4 + 4 * HID + HID + HH) * sizeof(float)
        + RT * sizeof(int);
    cudaFuncSetAttribute(mlp_scatter_kernel,
                         cudaFuncAttributeMaxDynamicSharedMemorySize,
                         (int)smem_bytes);

    setup_kernel<<<1, 64>>>(npf);
    zerofill_kernel<<<BB * NMAXX, 256>>>(npf, out);
    mlp_scatter_kernel<<<ngroups, NTHREADS, smem_bytes>>>(bbox, W1, b1, W2, b2,
                                                          out, N, ngroups);
    (void)n_in; (void)out_size;
}

// round 3
// speedup vs baseline: 2.9751x; 2.9751x over previous
#include <cuda_runtime.h>
#include <cuda_bf16.h>
#include <cstdint>

#define BB 64
#define TT 32
#define NMAXX 64
#define HH 256      // output dim (N of GEMM)
#define HID 128     // mid dim (K of GEMM)
#define MT 128      // rows per CTA tile
#define NTH 256     // 8 warps: 2 (M) x 4 (N), warp tile 64x64

// dynamic smem layout (1024-aligned):
//   A_hi [128][128] bf16 = 32KB,  A_lo 32KB,  B_hi [256][128] bf16 = 64KB, B_lo 64KB
#define OFF_ALO 32768
#define OFF_BHI 65536
#define OFF_BLO 131072
#define DYN_SMEM (196608 + 1024)

__device__ int g_orow[BB * NMAXX];

__global__ void setup_kernel(const int* __restrict__ npf) {
    __shared__ int sn[BB], st[BB];
    int tid = threadIdx.x;
    if (tid < BB) sn[tid] = npf[tid];
    __syncthreads();
    if (tid < BB) { int s = 0; for (int i = 0; i < tid; ++i) s += sn[i]; st[tid] = s; }
    __syncthreads();
    for (int idx = tid; idx < BB * NMAXX; idx += blockDim.x) {
        int b = idx >> 6, s = idx & 63;
        if (s < sn[b]) g_orow[st[b] + s] = s * (BB * TT) + b * TT;
    }
}

__global__ void zerofill_kernel(const int* __restrict__ npf, float* __restrict__ out) {
    int b = blockIdx.x >> 6, slot = blockIdx.x & 63;
    if (slot < npf[b]) return;
    float4* dst = reinterpret_cast<float4*>(out + ((size_t)slot * (BB * TT) + (size_t)b * TT) * HH);
    float4 z = make_float4(0.f, 0.f, 0.f, 0.f);
    for (int i = threadIdx.x; i < TT * HH / 4; i += blockDim.x) dst[i] = z;
}

__device__ __forceinline__ uint32_t smem_u32(const void* p) {
    uint32_t a;
    asm("{ .reg .u64 t; cvta.to.shared.u64 t, %1; cvt.u32.u64 %0, t; }" : "=r"(a) : "l"(p));
    return a;
}
__device__ __forceinline__ void sts32(uint32_t a, uint32_t v) {
    asm volatile("st.shared.b32 [%0], %1;" :: "r"(a), "r"(v) : "memory");
}
__device__ __forceinline__ void sts128(uint32_t a, uint4 v) {
    asm volatile("st.shared.v4.b32 [%0], {%1,%2,%3,%4};" :: "r"(a), "r"(v.x), "r"(v.y), "r"(v.z), "r"(v.w) : "memory");
}
__device__ __forceinline__ uint4 ldsm4(uint32_t a) {
    uint4 r;
    asm volatile("ldmatrix.sync.aligned.m8n8.x4.shared.b16 {%0,%1,%2,%3}, [%4];"
                 : "=r"(r.x), "=r"(r.y), "=r"(r.z), "=r"(r.w) : "r"(a));
    return r;
}
#define MMA(c, a, bb0, bb1) \
    asm volatile("mma.sync.aligned.m16n8k16.row.col.f32.bf16.bf16.f32 " \
                 "{%0,%1,%2,%3},{%4,%5,%6,%7},{%8,%9},{%0,%1,%2,%3};" \
                 : "+f"((c)[0]), "+f"((c)[1]), "+f"((c)[2]), "+f"((c)[3]) \
                 : "r"((a).x), "r"((a).y), "r"((a).z), "r"((a).w), "r"(bb0), "r"(bb1))

__global__ __launch_bounds__(NTH, 1)
void mma_kernel(const float* __restrict__ bbox,
                const float* __restrict__ W1, const float* __restrict__ b1,
                const float* __restrict__ W2, const float* __restrict__ b2,
                float* __restrict__ out, int TOTROWS, int ntiles) {
    extern __shared__ char smraw[];
    __shared__ float W1s[4 * HID], b1s[HID], b2s[HH];
    __shared__ int orow_s[MT];

    const int tid = threadIdx.x;
    const int lane = tid & 31, wid = tid >> 5;

    const uint32_t sb  = (smem_u32(smraw) + 1023) & ~1023u;
    const uint32_t A_HI = sb, B_HI = sb + OFF_BHI;

    // ---- stage small weights ----
    for (int i = tid; i < 4 * HID; i += NTH) W1s[i] = W1[i];
    if (tid < HID) b1s[tid] = b1[tid];
    if (tid < HH)  b2s[tid] = b2[tid];

    // ---- convert B = W2^T -> bf16 hi/lo, [n=256][k=128], 16B-chunk XOR swizzle ----
    {
        const int n = tid;                       // output column = B row
        const uint32_t nb = (uint32_t)n * 256u;  // 256B per row
        const uint32_t nx = (uint32_t)(n & 7);
        #pragma unroll 4
        for (int jp = 0; jp < 64; ++jp) {
            int j = 2 * jp;
            float w0 = W2[(size_t)j * HH + n];
            float w1 = W2[(size_t)(j + 1) * HH + n];
            __nv_bfloat162 hi = __floats2bfloat162_rn(w0, w1);
            float l0 = w0 - __bfloat162float(hi.x);
            float l1 = w1 - __bfloat162float(hi.y);
            __nv_bfloat162 lo = __floats2bfloat162_rn(l0, l1);
            uint32_t byte = nb + ((uint32_t)((jp >> 2) ^ nx) << 4) + (uint32_t)((jp & 3) << 2);
            sts32(B_HI + byte,           *reinterpret_cast<uint32_t*>(&hi));
            sts32(B_HI + 65536u + byte,  *reinterpret_cast<uint32_t*>(&lo));
        }
    }

    // ---- per-thread ldmatrix / epilogue geometry ----
    const int m0 = (wid >> 2) * 64;          // warp M origin
    const int n0 = (wid & 3) * 64;           // warp N origin
    const uint32_t xorv = (uint32_t)(lane & 7);
    const int a_row = (lane & 7) + ((lane >> 3) & 1) * 8;
    const uint32_t a_chi = (uint32_t)(lane >> 4);
    const int b_row = (lane & 7) + (lane >> 4) * 8;
    const uint32_t b_chi = (uint32_t)((lane >> 3) & 1);

    uint32_t aBase[4], bBase[4];
    #pragma unroll
    for (int mf = 0; mf < 4; ++mf) aBase[mf] = A_HI + (uint32_t)(m0 + mf * 16 + a_row) * 256u;
    #pragma unroll
    for (int nf = 0; nf < 4; ++nf) bBase[nf] = B_HI + (uint32_t)(n0 + nf * 16 + b_row) * 256u;

    // A-convert geometry
    const int cr   = tid & 127;              // row within tile
    const int half = tid >> 7;               // K half (j in [half*64, half*64+64))
    const uint32_t crb = (uint32_t)cr * 256u;
    const uint32_t crx = (uint32_t)(cr & 7);

    __syncthreads();  // B + weights visible

    for (int tile = blockIdx.x; tile < ntiles; tile += gridDim.x) {
        __syncthreads();  // previous tile's A readers done

        // ---- layer 1 fused + bf16 split into A_hi/A_lo ----
        {
            int grow = tile * MT + cr;
            float4 x = make_float4(0.f, 0.f, 0.f, 0.f);
            if (grow < TOTROWS) x = __ldg(reinterpret_cast<const float4*>(bbox) + grow);
            if (half == 0)
                orow_s[cr] = (grow < TOTROWS) ? (g_orow[grow >> 5] + (grow & 31)) : -1;
            #pragma unroll
            for (int cc = 0; cc < 8; ++cc) {
                int j0 = half * 64 + cc * 8;
                uint32_t hiw[4], low[4];
                #pragma unroll
                for (int p = 0; p < 4; ++p) {
                    int j = j0 + 2 * p;
                    float h0 = fmaf(x.x, W1s[j],     fmaf(x.y, W1s[HID + j],     fmaf(x.z, W1s[2 * HID + j],     fmaf(x.w, W1s[3 * HID + j],     b1s[j]))));
                    float h1 = fmaf(x.x, W1s[j + 1], fmaf(x.y, W1s[HID + j + 1], fmaf(x.z, W1s[2 * HID + j + 1], fmaf(x.w, W1s[3 * HID + j + 1], b1s[j + 1]))));
                    h0 = fmaxf(h0, 0.f); h1 = fmaxf(h1, 0.f);
                    __nv_bfloat162 hi = __floats2bfloat162_rn(h0, h1);
                    float l0 = h0 - __bfloat162float(hi.x);
                    float l1 = h1 - __bfloat162float(hi.y);
                    __nv_bfloat162 lo = __floats2bfloat162_rn(l0, l1);
                    hiw[p] = *reinterpret_cast<uint32_t*>(&hi);
                    low[p] = *reinterpret_cast<uint32_t*>(&lo);
                }
                uint32_t chunk = (uint32_t)(half * 8 + cc);
                uint32_t byte = crb + ((chunk ^ crx) << 4);
                sts128(A_HI + byte,           make_uint4(hiw[0], hiw[1], hiw[2], hiw[3]));
                sts128(A_HI + 32768u + byte,  make_uint4(low[0], low[1], low[2], low[3]));
            }
        }
        __syncthreads();

        // ---- MMA mainloop: 3-product bf16 split, K=128 ----
        float acc[4][8][4];
        #pragma unroll
        for (int mf = 0; mf < 4; ++mf)
            #pragma unroll
            for (int nf = 0; nf < 8; ++nf)
                #pragma unroll
                for (int q = 0; q < 4; ++q) acc[mf][nf][q] = 0.f;

        #pragma unroll 1
        for (int kc = 0; kc < 8; ++kc) {
            uint32_t kxa = ((((uint32_t)kc << 1) + a_chi) ^ xorv) << 4;
            uint32_t kxb = ((((uint32_t)kc << 1) + b_chi) ^ xorv) << 4;
            uint4 ah[4], bh[4], bl[4], al[4];
            #pragma unroll
            for (int mf = 0; mf < 4; ++mf) ah[mf] = ldsm4(aBase[mf] + kxa);
            #pragma unroll
            for (int nf = 0; nf < 4; ++nf) bh[nf] = ldsm4(bBase[nf] + kxb);
            // P1: A_hi x B_hi
            #pragma unroll
            for (int mf = 0; mf < 4; ++mf)
                #pragma unroll
                for (int nf = 0; nf < 4; ++nf) {
                    MMA(acc[mf][2 * nf],     ah[mf], bh[nf].x, bh[nf].y);
                    MMA(acc[mf][2 * nf + 1], ah[mf], bh[nf].z, bh[nf].w);
                }
            #pragma unroll
            for (int nf = 0; nf < 4; ++nf) bl[nf] = ldsm4(bBase[nf] + 65536u + kxb);
            // P2: A_hi x B_lo
            #pragma unroll
            for (int mf = 0; mf < 4; ++mf)
                #pragma unroll
                for (int nf = 0; nf < 4; ++nf) {
                    MMA(acc[mf][2 * nf],     ah[mf], bl[nf].x, bl[nf].y);
                    MMA(acc[mf][2 * nf + 1], ah[mf], bl[nf].z, bl[nf].w);
                }
            #pragma unroll
            for (int mf = 0; mf < 4; ++mf) al[mf] = ldsm4(aBase[mf] + 32768u + kxa);
            // P3: A_lo x B_hi
            #pragma unroll
            for (int mf = 0; mf < 4; ++mf)
                #pragma unroll
                for (int nf = 0; nf < 4; ++nf) {
                    MMA(acc[mf][2 * nf],     al[mf], bh[nf].x, bh[nf].y);
                    MMA(acc[mf][2 * nf + 1], al[mf], bh[nf].z, bh[nf].w);
                }
        }

        // ---- epilogue: + b2, scatter rows ----
        const int cbase = n0 + (lane & 3) * 2;
        #pragma unroll
        for (int mf = 0; mf < 4; ++mf) {
            int r1 = m0 + mf * 16 + (lane >> 2);
            int row1 = orow_s[r1];
            int row2 = orow_s[r1 + 8];
            #pragma unroll
            for (int nf = 0; nf < 8; ++nf) {
                int col = cbase + nf * 8;
                float bx = b2s[col], by = b2s[col + 1];
                if (row1 >= 0) {
                    float2 v = make_float2(acc[mf][nf][0] + bx, acc[mf][nf][1] + by);
                    *reinterpret_cast<float2*>(out + (size_t)row1 * HH + col) = v;
                }
                if (row2 >= 0) {
                    float2 v = make_float2(acc[mf][nf][2] + bx, acc[mf][nf][3] + by);
                    *reinterpret_cast<float2*>(out + (size_t)row2 * HH + col) = v;
                }
            }
        }
    }
}

extern "C" void kernel_launch(void* const* d_in, const int* in_sizes, int n_in,
                              void* d_out, int out_size) {
    const float* bbox = (const float*)d_in[0];
    const float* W1   = (const float*)d_in[1];
    const float* b1   = (const float*)d_in[2];
    const float* W2   = (const float*)d_in[3];
    const float* b2   = (const float*)d_in[4];
    const int*   npf  = (const int*)d_in[5];
    float* out = (float*)d_out;

    const int TOTROWS = in_sizes[0] / 4;               // N * T rows
    const int ntiles  = (TOTROWS + MT - 1) / MT;

    int nsm = 148;
    cudaDeviceGetAttribute(&nsm, cudaDevAttrMultiProcessorCount, 0);
    int grid = ntiles < nsm ? ntiles : nsm;

    cudaFuncSetAttribute(mma_kernel, cudaFuncAttributeMaxDynamicSharedMemorySize, DYN_SMEM);

    setup_kernel<<<1, 256>>>(npf);
    zerofill_kernel<<<BB * NMAXX, 256>>>(npf, out);
    mma_kernel<<<grid, NTH, DYN_SMEM>>>(bbox, W1, b1, W2, b2, out, TOTROWS, ntiles);
    (void)n_in; (void)out_size;
}

// round 4
// speedup vs baseline: 3.3647x; 1.1310x over previous
#include <cuda_runtime.h>
#include <cuda_fp16.h>
#include <cstdint>

#define BB 64
#define TT 32
#define NMAXX 64
#define HH 256      // output dim (N of GEMM)
#define HID 128     // mid dim (K of GEMM)
#define MT 128      // rows per CTA tile
#define NTH 256     // 8 warps: 2 (M) x 4 (N), warp tile 64x64

// dynamic smem (1024-aligned): A_hi[128][128]f16=32KB, B_hi[256][128]f16=64KB, B_lo 64KB
#define OFF_BHI 32768
#define OFF_BLO 98304
#define DYN_SMEM (163840 + 1024)

__device__ __forceinline__ uint32_t smem_u32(const void* p) {
    uint32_t a;
    asm("{ .reg .u64 t; cvta.to.shared.u64 t, %1; cvt.u32.u64 %0, t; }" : "=r"(a) : "l"(p));
    return a;
}
__device__ __forceinline__ void sts32(uint32_t a, uint32_t v) {
    asm volatile("st.shared.b32 [%0], %1;" :: "r"(a), "r"(v) : "memory");
}
__device__ __forceinline__ void sts128(uint32_t a, uint4 v) {
    asm volatile("st.shared.v4.b32 [%0], {%1,%2,%3,%4};" :: "r"(a), "r"(v.x), "r"(v.y), "r"(v.z), "r"(v.w) : "memory");
}
__device__ __forceinline__ uint4 ldsm4(uint32_t a) {
    uint4 r;
    asm volatile("ldmatrix.sync.aligned.m8n8.x4.shared.b16 {%0,%1,%2,%3}, [%4];"
                 : "=r"(r.x), "=r"(r.y), "=r"(r.z), "=r"(r.w) : "r"(a));
    return r;
}
#define MMA(c, a, bb0, bb1) \
    asm volatile("mma.sync.aligned.m16n8k16.row.col.f32.f16.f16.f32 " \
                 "{%0,%1,%2,%3},{%4,%5,%6,%7},{%8,%9},{%0,%1,%2,%3};" \
                 : "+f"((c)[0]), "+f"((c)[1]), "+f"((c)[2]), "+f"((c)[3]) \
                 : "r"((a).x), "r"((a).y), "r"((a).z), "r"((a).w), "r"(bb0), "r"(bb1))

__global__ __launch_bounds__(NTH, 1)
void fused_kernel(const float* __restrict__ bbox,
                  const float* __restrict__ W1, const float* __restrict__ b1,
                  const float* __restrict__ W2, const float* __restrict__ b2,
                  const int* __restrict__ npf,
                  float* __restrict__ out, int TOTROWS, int ntiles) {
    extern __shared__ char smraw[];
    __shared__ float W1s[4 * HID], b1s[HID], b2s[HH];
    __shared__ int sn[BB], st[BB + 1];
    __shared__ int orow_s[MT];

    const int tid = threadIdx.x;
    const int lane = tid & 31, wid = tid >> 5;

    const uint32_t sb   = (smem_u32(smraw) + 1023) & ~1023u;
    const uint32_t A_HI = sb;
    const uint32_t B_HI = sb + OFF_BHI;
    const uint32_t B_LO = sb + OFF_BLO;

    // ---- stage small weights + batch counts ----
    for (int i = tid; i < 4 * HID; i += NTH) W1s[i] = W1[i];
    if (tid < HID) b1s[tid] = b1[tid];
    if (tid < HH)  b2s[tid] = b2[tid];
    if (tid < BB)  sn[tid] = npf[tid];
    __syncthreads();

    // ---- zerofill padded slots (round-robin over CTAs), overlaps with B convert ----
    for (int p = blockIdx.x; p < BB * NMAXX; p += gridDim.x) {
        int b = p >> 6, s = p & 63;
        if (s < sn[b]) continue;
        float4* dst = reinterpret_cast<float4*>(out + ((size_t)s * (BB * TT) + (size_t)b * TT) * HH);
        float4 z = make_float4(0.f, 0.f, 0.f, 0.f);
        #pragma unroll
        for (int i = 0; i < 8; ++i) dst[tid + i * NTH] = z;
    }

    // ---- exclusive scan (thread 0, overlapped with B convert by other threads) ----
    if (tid == 0) {
        int s = 0;
        #pragma unroll
        for (int i = 0; i < BB; ++i) { st[i] = s; s += sn[i]; }
        st[BB] = s;
    }

    // ---- convert B = W2^T -> f16 hi/lo, permuted rows + 16B XOR swizzle ----
    {
        const int n = tid;                 // real output column
        const int r = n & 63;
        const int s = (((r >> 1) & 7) << 3) + ((r >> 4) << 1) + (r & 1);  // mma row within 64-block
        const int m = (n & ~63) | s;
        const uint32_t mb = (uint32_t)m * 256u;
        const uint32_t mx = (uint32_t)(m & 7);
        #pragma unroll 4
        for (int jp = 0; jp < 64; ++jp) {
            int j = 2 * jp;
            float w0 = __ldg(&W2[(size_t)j * HH + n]);
            float w1 = __ldg(&W2[(size_t)(j + 1) * HH + n]);
            __half2 hi = __floats2half2_rn(w0, w1);
            float l0 = w0 - __half2float(__low2half(hi));
            float l1 = w1 - __half2float(__high2half(hi));
            __half2 lo = __floats2half2_rn(l0, l1);
            uint32_t byte = mb + ((((uint32_t)jp >> 2) ^ mx) << 4) + (((uint32_t)jp & 3) << 2);
            sts32(B_HI + byte, *reinterpret_cast<uint32_t*>(&hi));
            sts32(B_LO + byte, *reinterpret_cast<uint32_t*>(&lo));
        }
    }

    // ---- per-thread geometry ----
    const int m0 = (wid >> 2) * 64;           // warp M origin
    const int n0 = (wid & 3) * 64;            // warp N origin
    const uint32_t xorv = (uint32_t)(lane & 7);
    const int a_row = (lane & 7) + ((lane >> 3) & 1) * 8;
    const uint32_t a_chi = (uint32_t)(lane >> 4);
    const int b_row = (lane & 7) + (lane >> 4) * 8;
    const uint32_t b_chi = (uint32_t)((lane >> 3) & 1);

    uint32_t aBase[4], bBase[4];
    #pragma unroll
    for (int mf = 0; mf < 4; ++mf) aBase[mf] = A_HI + (uint32_t)(m0 + mf * 16 + a_row) * 256u;
    #pragma unroll
    for (int nf = 0; nf < 4; ++nf) bBase[nf] = B_HI + (uint32_t)(n0 + nf * 16 + b_row) * 256u;

    // A-convert geometry
    const int cr    = tid & 127;              // row within tile
    const int khalf = tid >> 7;               // K half
    const uint32_t crb = (uint32_t)cr * 256u;
    const uint32_t crx = (uint32_t)(cr & 7);

    const int cb = n0 + (lane & 3) * 16;      // epilogue contiguous col base

    __syncthreads();  // B, scan, weights visible

    for (int tile = blockIdx.x; tile < ntiles; tile += gridDim.x) {
        __syncthreads();  // previous tile's A readers done

        // ---- layer 1 fused + fp16 hi into A ----
        {
            int grow = tile * MT + cr;
            float4 x = make_float4(0.f, 0.f, 0.f, 0.f);
            if (grow < TOTROWS) x = __ldg(reinterpret_cast<const float4*>(bbox) + grow);
            if (khalf == 0) {
                int orow = -1;
                if (grow < TOTROWS) {
                    int box = grow >> 5;
                    int lo = 0, hi = BB - 1;
                    #pragma unroll
                    for (int step = 0; step < 6; ++step) {
                        int mid = (lo + hi + 1) >> 1;
                        if (st[mid] <= box) lo = mid; else hi = mid - 1;
                    }
                    orow = (box - st[lo]) * (BB * TT) + lo * TT + (grow & 31);
                }
                orow_s[cr] = orow;
            }
            #pragma unroll
            for (int cc = 0; cc < 8; ++cc) {
                int j0 = khalf * 64 + cc * 8;
                uint32_t hiw[4];
                #pragma unroll
                for (int p = 0; p < 4; ++p) {
                    int j = j0 + 2 * p;
                    float h0 = fmaf(x.x, W1s[j],     fmaf(x.y, W1s[HID + j],     fmaf(x.z, W1s[2 * HID + j],     fmaf(x.w, W1s[3 * HID + j],     b1s[j]))));
                    float h1 = fmaf(x.x, W1s[j + 1], fmaf(x.y, W1s[HID + j + 1], fmaf(x.z, W1s[2 * HID + j + 1], fmaf(x.w, W1s[3 * HID + j + 1], b1s[j + 1]))));
                    __half2 hi = __floats2half2_rn(fmaxf(h0, 0.f), fmaxf(h1, 0.f));
                    hiw[p] = *reinterpret_cast<uint32_t*>(&hi);
                }
                uint32_t chunk = (uint32_t)(khalf * 8 + cc);
                uint32_t byte = crb + ((chunk ^ crx) << 4);
                sts128(A_HI + byte, make_uint4(hiw[0], hiw[1], hiw[2], hiw[3]));
            }
        }
        __syncthreads();

        // ---- MMA mainloop: Ahi*Bhi + Ahi*Blo, K=128 ----
        float acc[4][8][4];
        #pragma unroll
        for (int mf = 0; mf < 4; ++mf)
            #pragma unroll
            for (int q = 0; q < 8; ++q)
                #pragma unroll
                for (int e = 0; e < 4; ++e) acc[mf][q][e] = 0.f;

        #pragma unroll 1
        for (int kc = 0; kc < 8; ++kc) {
            uint32_t kxa = ((((uint32_t)kc << 1) + a_chi) ^ xorv) << 4;
            uint32_t kxb = ((((uint32_t)kc << 1) + b_chi) ^ xorv) << 4;
            uint4 ah[4], bh[4], bl[4];
            #pragma unroll
            for (int mf = 0; mf < 4; ++mf) ah[mf] = ldsm4(aBase[mf] + kxa);
            #pragma unroll
            for (int nf = 0; nf < 4; ++nf) bh[nf] = ldsm4(bBase[nf] + kxb);
            #pragma unroll
            for (int mf = 0; mf < 4; ++mf)
                #pragma unroll
                for (int nf = 0; nf < 4; ++nf) {
                    MMA(acc[mf][2 * nf],     ah[mf], bh[nf].x, bh[nf].y);
                    MMA(acc[mf][2 * nf + 1], ah[mf], bh[nf].z, bh[nf].w);
                }
            #pragma unroll
            for (int nf = 0; nf < 4; ++nf) bl[nf] = ldsm4(bBase[nf] + (OFF_BLO - OFF_BHI) + kxb);
            #pragma unroll
            for (int mf = 0; mf < 4; ++mf)
                #pragma unroll
                for (int nf = 0; nf < 4; ++nf) {
                    MMA(acc[mf][2 * nf],     ah[mf], bl[nf].x, bl[nf].y);
                    MMA(acc[mf][2 * nf + 1], ah[mf], bl[nf].z, bl[nf].w);
                }
        }

        // ---- epilogue: + b2, contiguous 16-col stores per thread ----
        #pragma unroll
        for (int mf = 0; mf < 4; ++mf) {
            int r1 = m0 + mf * 16 + (lane >> 2);
            int row1 = orow_s[r1];
            int row2 = orow_s[r1 + 8];
            #pragma unroll
            for (int u = 0; u < 4; ++u) {
                float4 bv = *reinterpret_cast<float4*>(&b2s[cb + 4 * u]);
                if (row1 >= 0) {
                    float4 v;
                    v.x = acc[mf][2 * u][0] + bv.x;
                    v.y = acc[mf][2 * u][1] + bv.y;
                    v.z = acc[mf][2 * u + 1][0] + bv.z;
                    v.w = acc[mf][2 * u + 1][1] + bv.w;
                    *reinterpret_cast<float4*>(out + (size_t)row1 * HH + cb + 4 * u) = v;
                }
                if (row2 >= 0) {
                    float4 v;
                    v.x = acc[mf][2 * u][2] + bv.x;
                    v.y = acc[mf][2 * u][3] + bv.y;
                    v.z = acc[mf][2 * u + 1][2] + bv.z;
                    v.w = acc[mf][2 * u + 1][3] + bv.w;
                    *reinterpret_cast<float4*>(out + (size_t)row2 * HH + cb + 4 * u) = v;
                }
            }
        }
    }
}

extern "C" void kernel_launch(void* const* d_in, const int* in_sizes, int n_in,
                              void* d_out, int out_size) {
    const float* bbox = (const float*)d_in[0];
    const float* W1   = (const float*)d_in[1];
    const float* b1   = (const float*)d_in[2];
    const float* W2   = (const float*)d_in[3];
    const float* b2   = (const float*)d_in[4];
    const int*   npf  = (const int*)d_in[5];
    float* out = (float*)d_out;

    const int TOTROWS = in_sizes[0] / 4;               // N * T rows
    const int ntiles  = (TOTROWS + MT - 1) / MT;

    int nsm = 148;
    cudaDeviceGetAttribute(&nsm, cudaDevAttrMultiProcessorCount, 0);

    cudaFuncSetAttribute(fused_kernel, cudaFuncAttributeMaxDynamicSharedMemorySize, DYN_SMEM);
    fused_kernel<<<nsm, NTH, DYN_SMEM>>>(bbox, W1, b1, W2, b2, npf, out, TOTROWS, ntiles);
    (void)n_in; (void)out_size;
}

// round 5
// speedup vs baseline: 4.1482x; 1.2329x over previous
#include <cuda_runtime.h>
#include <cuda_fp16.h>
#include <cstdint>

#define BB 64
#define TT 32
#define NMAXX 64
#define HH 256      // output dim (N of GEMM)
#define HID 128     // mid dim (K of GEMM)
#define MT 64       // rows per half-tile
#define NTH 512     // 16 warps: two independent halves of 8 warps

// dynamic smem (1024-aligned): A0[64][128]f16=16KB, A1=16KB, B_hi[256][128]f16=64KB, B_lo=64KB
#define OFF_A1  16384
#define OFF_BHI 32768
#define OFF_BLO 98304
#define DYN_SMEM (163840 + 1024)

__device__ __forceinline__ uint32_t smem_u32(const void* p) {
    uint32_t a;
    asm("{ .reg .u64 t; cvta.to.shared.u64 t, %1; cvt.u32.u64 %0, t; }" : "=r"(a) : "l"(p));
    return a;
}
__device__ __forceinline__ void sts32(uint32_t a, uint32_t v) {
    asm volatile("st.shared.b32 [%0], %1;" :: "r"(a), "r"(v) : "memory");
}
__device__ __forceinline__ void sts128(uint32_t a, uint4 v) {
    asm volatile("st.shared.v4.b32 [%0], {%1,%2,%3,%4};" :: "r"(a), "r"(v.x), "r"(v.y), "r"(v.z), "r"(v.w) : "memory");
}
__device__ __forceinline__ uint4 ldsm4(uint32_t a) {
    uint4 r;
    asm volatile("ldmatrix.sync.aligned.m8n8.x4.shared.b16 {%0,%1,%2,%3}, [%4];"
                 : "=r"(r.x), "=r"(r.y), "=r"(r.z), "=r"(r.w) : "r"(a));
    return r;
}
#define MMA(c, a0, a1, bb0, bb1) \
    asm volatile("mma.sync.aligned.m16n8k16.row.col.f32.f16.f16.f32 " \
                 "{%0,%1,%2,%3},{%4,%5,%6,%7},{%8,%9},{%0,%1,%2,%3};" \
                 : "+f"((c)[0]), "+f"((c)[1]), "+f"((c)[2]), "+f"((c)[3]) \
                 : "r"(a0), "r"(a1), "r"((a).z), "r"((a).w), "r"(bb0), "r"(bb1))
#define MMA4(c, a, bb0, bb1) \
    asm volatile("mma.sync.aligned.m16n8k16.row.col.f32.f16.f16.f32 " \
                 "{%0,%1,%2,%3},{%4,%5,%6,%7},{%8,%9},{%0,%1,%2,%3};" \
                 : "+f"((c)[0]), "+f"((c)[1]), "+f"((c)[2]), "+f"((c)[3]) \
                 : "r"((a).x), "r"((a).y), "r"((a).z), "r"((a).w), "r"(bb0), "r"(bb1))

__global__ __launch_bounds__(NTH, 1)
void fused_kernel(const float* __restrict__ bbox,
                  const float* __restrict__ W1, const float* __restrict__ b1,
                  const float* __restrict__ W2, const float* __restrict__ b2,
                  const int* __restrict__ npf,
                  float* __restrict__ out, int TOTROWS, int ntiles) {
    extern __shared__ char smraw[];
    __shared__ float W1s[4 * HID], b1s[HID], b2s[HH];
    __shared__ int sn[BB], st[BB + 1];
    __shared__ int orow_s[2][MT];

    const int tid  = threadIdx.x;
    const int lane = tid & 31, wid = tid >> 5;
    const int half = wid >> 3;        // 0 or 1: independent half-block
    const int hw   = wid & 7;         // warp within half
    const int htid = tid & 255;       // thread within half

    const uint32_t sb   = (smem_u32(smraw) + 1023) & ~1023u;
    const uint32_t A_H  = sb + (half ? OFF_A1 : 0);
    const uint32_t B_HI = sb + OFF_BHI;
    const uint32_t B_LO = sb + OFF_BLO;

    // ---- stage small weights + batch counts ----
    for (int i = tid; i < 4 * HID; i += NTH) W1s[i] = W1[i];
    if (tid < HID) b1s[tid] = b1[tid];
    if (tid >= HID && tid < HID + HH) b2s[tid - HID] = b2[tid - HID];
    if (tid >= HID + HH && tid < HID + HH + BB) sn[tid - HID - HH] = npf[tid - HID - HH];
    __syncthreads();

    // ---- zerofill padded slots (round-robin over CTAs), overlaps with B convert ----
    for (int p = blockIdx.x; p < BB * NMAXX; p += gridDim.x) {
        int b = p >> 6, s = p & 63;
        if (s < sn[b]) continue;
        float4* dst = reinterpret_cast<float4*>(out + ((size_t)s * (BB * TT) + (size_t)b * TT) * HH);
        float4 z = make_float4(0.f, 0.f, 0.f, 0.f);
        #pragma unroll
        for (int i = 0; i < 4; ++i) dst[tid + i * NTH] = z;
    }

    // ---- exclusive scan (thread 0) ----
    if (tid == 0) {
        int s = 0;
        #pragma unroll
        for (int i = 0; i < BB; ++i) { st[i] = s; s += sn[i]; }
        st[BB] = s;
    }

    // ---- convert B = W2^T -> f16 hi/lo, permuted rows + 16B XOR swizzle ----
    {
        const int n  = tid & 255;          // real output column
        const int kh = tid >> 8;           // K half (32 pairs each)
        const int r = n & 63;
        const int s = (((r >> 1) & 7) << 3) + ((r >> 4) << 1) + (r & 1);  // mma row within 64-block
        const int m = (n & ~63) | s;
        const uint32_t mb = (uint32_t)m * 256u;
        const uint32_t mx = (uint32_t)(m & 7);
        #pragma unroll 4
        for (int q = 0; q < 32; ++q) {
            int jp = kh * 32 + q;
            int j = 2 * jp;
            float w0 = __ldg(&W2[(size_t)j * HH + n]);
            float w1 = __ldg(&W2[(size_t)(j + 1) * HH + n]);
            __half2 hi = __floats2half2_rn(w0, w1);
            float l0 = w0 - __half2float(__low2half(hi));
            float l1 = w1 - __half2float(__high2half(hi));
            __half2 lo = __floats2half2_rn(l0, l1);
            uint32_t byte = mb + ((((uint32_t)jp >> 2) ^ mx) << 4) + (((uint32_t)jp & 3) << 2);
            sts32(B_HI + byte, *reinterpret_cast<uint32_t*>(&hi));
            sts32(B_LO + byte, *reinterpret_cast<uint32_t*>(&lo));
        }
    }

    // ---- per-thread geometry (within half): 2(M) x 4(N) warps, warp tile 32x64 ----
    const int m0 = (hw >> 2) * 32;            // warp M origin in 64-row tile
    const int n0 = (hw & 3) * 64;             // warp N origin
    const uint32_t xorv = (uint32_t)(lane & 7);
    const int a_row = (lane & 7) + ((lane >> 3) & 1) * 8;
    const uint32_t a_chi = (uint32_t)(lane >> 4);
    const int b_row = (lane & 7) + (lane >> 4) * 8;
    const uint32_t b_chi = (uint32_t)((lane >> 3) & 1);

    uint32_t aBase[2], bBase[4];
    #pragma unroll
    for (int mf = 0; mf < 2; ++mf) aBase[mf] = A_H + (uint32_t)(m0 + mf * 16 + a_row) * 256u;
    #pragma unroll
    for (int nf = 0; nf < 4; ++nf) bBase[nf] = B_HI + (uint32_t)(n0 + nf * 16 + b_row) * 256u;

    // A-convert geometry (256 threads per half): row 0..63, k-quarter 0..3
    const int cr = htid & 63;
    const int kq = htid >> 6;
    const uint32_t crb = (uint32_t)cr * 256u;
    const uint32_t crx = (uint32_t)(cr & 7);

    const int cb = n0 + (lane & 3) * 16;      // epilogue contiguous col base
    const int barid = half + 1;

    __syncthreads();  // B, scan, weights visible; last full-block barrier

    const int sstride = gridDim.x * 2;
    for (int tile = blockIdx.x * 2 + half; tile < ntiles; tile += sstride) {
        asm volatile("bar.sync %0, %1;" :: "r"(barid), "r"(256) : "memory");  // A readers done

        // ---- layer 1 fused + fp16 hi into A ----
        {
            int grow = tile * MT + cr;
            float4 x = make_float4(0.f, 0.f, 0.f, 0.f);
            if (grow < TOTROWS) x = __ldg(reinterpret_cast<const float4*>(bbox) + grow);
            if (kq == 0) {
                int orow = -1;
                if (grow < TOTROWS) {
                    int box = grow >> 5;
                    int lo = 0, hi = BB - 1;
                    #pragma unroll
                    for (int step = 0; step < 6; ++step) {
                        int mid = (lo + hi + 1) >> 1;
                        if (st[mid] <= box) lo = mid; else hi = mid - 1;
                    }
                    orow = (box - st[lo]) * (BB * TT) + lo * TT + (grow & 31);
                }
                orow_s[half][cr] = orow;
            }
            #pragma unroll
            for (int cc = 0; cc < 4; ++cc) {
                int chunk = kq * 4 + cc;
                int j0 = chunk * 8;
                uint32_t hiw[4];
                #pragma unroll
                for (int p = 0; p < 4; ++p) {
                    int j = j0 + 2 * p;
                    float h0 = fmaf(x.x, W1s[j],     fmaf(x.y, W1s[HID + j],     fmaf(x.z, W1s[2 * HID + j],     fmaf(x.w, W1s[3 * HID + j],     b1s[j]))));
                    float h1 = fmaf(x.x, W1s[j + 1], fmaf(x.y, W1s[HID + j + 1], fmaf(x.z, W1s[2 * HID + j + 1], fmaf(x.w, W1s[3 * HID + j + 1], b1s[j + 1]))));
                    __half2 hi = __floats2half2_rn(fmaxf(h0, 0.f), fmaxf(h1, 0.f));
                    hiw[p] = *reinterpret_cast<uint32_t*>(&hi);
                }
                uint32_t byte = crb + (((uint32_t)chunk ^ crx) << 4);
                sts128(A_H + byte, make_uint4(hiw[0], hiw[1], hiw[2], hiw[3]));
            }
        }
        asm volatile("bar.sync %0, %1;" :: "r"(barid), "r"(256) : "memory");

        // ---- MMA mainloop: Ahi*Bhi + Ahi*Blo, K=128 ----
        float acc[2][8][4];
        #pragma unroll
        for (int mf = 0; mf < 2; ++mf)
            #pragma unroll
            for (int q = 0; q < 8; ++q)
                #pragma unroll
                for (int e = 0; e < 4; ++e) acc[mf][q][e] = 0.f;

        #pragma unroll 1
        for (int kc = 0; kc < 8; ++kc) {
            uint32_t kxa = ((((uint32_t)kc << 1) + a_chi) ^ xorv) << 4;
            uint32_t kxb = ((((uint32_t)kc << 1) + b_chi) ^ xorv) << 4;
            uint4 ah[2], bh[4], bl[4];
            #pragma unroll
            for (int mf = 0; mf < 2; ++mf) ah[mf] = ldsm4(aBase[mf] + kxa);
            #pragma unroll
            for (int nf = 0; nf < 4; ++nf) bh[nf] = ldsm4(bBase[nf] + kxb);
            #pragma unroll
            for (int nf = 0; nf < 4; ++nf) bl[nf] = ldsm4(bBase[nf] + (OFF_BLO - OFF_BHI) + kxb);
            #pragma unroll
            for (int mf = 0; mf < 2; ++mf)
                #pragma unroll
                for (int nf = 0; nf < 4; ++nf) {
                    MMA4(acc[mf][2 * nf],     ah[mf], bh[nf].x, bh[nf].y);
                    MMA4(acc[mf][2 * nf + 1], ah[mf], bh[nf].z, bh[nf].w);
                }
            #pragma unroll
            for (int mf = 0; mf < 2; ++mf)
                #pragma unroll
                for (int nf = 0; nf < 4; ++nf) {
                    MMA4(acc[mf][2 * nf],     ah[mf], bl[nf].x, bl[nf].y);
                    MMA4(acc[mf][2 * nf + 1], ah[mf], bl[nf].z, bl[nf].w);
                }
        }

        // ---- epilogue: + b2, contiguous 16-col stores per thread ----
        #pragma unroll
        for (int mf = 0; mf < 2; ++mf) {
            int r1 = m0 + mf * 16 + (lane >> 2);
            int row1 = orow_s[half][r1];
            int row2 = orow_s[half][r1 + 8];
            #pragma unroll
            for (int u = 0; u < 4; ++u) {
                float4 bv = *reinterpret_cast<float4*>(&b2s[cb + 4 * u]);
                if (row1 >= 0) {
                    float4 v;
                    v.x = acc[mf][2 * u][0] + bv.x;
                    v.y = acc[mf][2 * u][1] + bv.y;
                    v.z = acc[mf][2 * u + 1][0] + bv.z;
                    v.w = acc[mf][2 * u + 1][1] + bv.w;
                    *reinterpret_cast<float4*>(out + (size_t)row1 * HH + cb + 4 * u) = v;
                }
                if (row2 >= 0) {
                    float4 v;
                    v.x = acc[mf][2 * u][2] + bv.x;
                    v.y = acc[mf][2 * u][3] + bv.y;
                    v.z = acc[mf][2 * u + 1][2] + bv.z;
                    v.w = acc[mf][2 * u + 1][3] + bv.w;
                    *reinterpret_cast<float4*>(out + (size_t)row2 * HH + cb + 4 * u) = v;
                }
            }
        }
    }
}

extern "C" void kernel_launch(void* const* d_in, const int* in_sizes, int n_in,
                              void* d_out, int out_size) {
    const float* bbox = (const float*)d_in[0];
    const float* W1   = (const float*)d_in[1];
    const float* b1   = (const float*)d_in[2];
    const float* W2   = (const float*)d_in[3];
    const float* b2   = (const float*)d_in[4];
    const int*   npf  = (const int*)d_in[5];
    float* out = (float*)d_out;

    const int TOTROWS = in_sizes[0] / 4;               // N * T rows
    const int ntiles  = (TOTROWS + MT - 1) / MT;       // 64-row tiles

    int nsm = 148;
    cudaDeviceGetAttribute(&nsm, cudaDevAttrMultiProcessorCount, 0);

    cudaFuncSetAttribute(fused_kernel, cudaFuncAttributeMaxDynamicSharedMemorySize, DYN_SMEM);
    fused_kernel<<<nsm, NTH, DYN_SMEM>>>(bbox, W1, b1, W2, b2, npf, out, TOTROWS, ntiles);
    (void)n_in; (void)out_size;
}